// round 2
// baseline (speedup 1.0000x reference)
#include <cuda_runtime.h>
#include <cstdint>
#include <cstdio>

#define Bsz  512
#define Tlen 128
#define Idim 512
#define Hdim 512
#define Cnum 97
#define Snum 26
#define ICdim (Idim + Cnum)   // 609

// ---------------- device scratch (allocation-free rule) ----------------
__device__ __align__(16) float g_feat[(size_t)Bsz * Tlen * Hdim];   // 128 MiB
__device__ __align__(16) float g_h[Bsz * Hdim];
__device__ __align__(16) float g_c[Bsz * Hdim];
__device__ __align__(16) float g_hp[Bsz * Hdim];
__device__ __align__(16) float g_alpha[Bsz * Tlen];
__device__ __align__(16) float g_ctx[Bsz * Idim];
__device__ __align__(16) float g_gates[Bsz * 4 * Hdim];
__device__ __align__(16) float g_outh[(size_t)Bsz * Snum * Hdim];

// ---------------- generic fp32 GEMM: C[m,n] (+)= sum_k A[m,k]*B[n,k] (+bias[n]) --
// A: [M,K] row-major (lda), B: [N,K] row-major (ldb) -> C = A * B^T
// BM=128, BN=64, BK=16, 256 threads, 8x4 microtile (cyclic mapping)
template<int ACC, int BIAS>
__global__ void __launch_bounds__(256) sgemm_tn(
    const float* __restrict__ A, int lda,
    const float* __restrict__ Bm, int ldb,
    float* __restrict__ C, int ldc,
    const float* __restrict__ bias,
    int M, int N, int K)
{
    const int BM = 128, BN = 64, BK = 16;
    __shared__ float As[BK][BM];
    __shared__ float Bs[BK][BN];
    int tid = threadIdx.x;
    int tx = tid & 15;        // n direction
    int ty = tid >> 4;        // m direction
    int m0 = blockIdx.y * BM;
    int n0 = blockIdx.x * BN;

    float acc[8][4];
#pragma unroll
    for (int i = 0; i < 8; i++)
#pragma unroll
        for (int j = 0; j < 4; j++) acc[i][j] = 0.f;

    for (int k0 = 0; k0 < K; k0 += BK) {
        // A tile: 128x16 = 512 float4, 2 per thread (M always multiple of 128 here)
#pragma unroll
        for (int i = 0; i < 2; i++) {
            int lin = tid + i * 256;
            int row = lin >> 2;
            int kc  = (lin & 3) << 2;
            const float4 v = *reinterpret_cast<const float4*>(
                &A[(size_t)(m0 + row) * lda + k0 + kc]);
            As[kc + 0][row] = v.x; As[kc + 1][row] = v.y;
            As[kc + 2][row] = v.z; As[kc + 3][row] = v.w;
        }
        // B tile: 64x16 = 1024 scalars, 4 per thread (scalar: ldb=609 is unaligned)
#pragma unroll
        for (int i = 0; i < 4; i++) {
            int lin = tid + i * 256;
            int kk = lin & 15;
            int nn = lin >> 4;
            float v = 0.f;
            if (n0 + nn < N) v = Bm[(size_t)(n0 + nn) * ldb + k0 + kk];
            Bs[kk][nn] = v;
        }
        __syncthreads();
#pragma unroll
        for (int kk = 0; kk < BK; kk++) {
            float a[8], b[4];
#pragma unroll
            for (int i = 0; i < 8; i++) a[i] = As[kk][ty + i * 16];
#pragma unroll
            for (int j = 0; j < 4; j++) b[j] = Bs[kk][tx + j * 16];
#pragma unroll
            for (int i = 0; i < 8; i++)
#pragma unroll
                for (int j = 0; j < 4; j++)
                    acc[i][j] += a[i] * b[j];
        }
        __syncthreads();
    }
#pragma unroll
    for (int i = 0; i < 8; i++) {
        int m = m0 + ty + i * 16;
#pragma unroll
        for (int j = 0; j < 4; j++) {
            int n = n0 + tx + j * 16;
            if (n < N) {
                float v = acc[i][j];
                if (BIAS) v += bias[n];
                float* cp = &C[(size_t)m * ldc + n];
                if (ACC) v += *cp;
                *cp = v;
            }
        }
    }
}

// ---------------- zero init of h,c ----------------
__global__ void zero_hc_kernel() {
    int i = blockIdx.x * 256 + threadIdx.x;   // 1024 x 256 = 262144 = Bsz*Hdim
    g_h[i] = 0.f;
    g_c[i] = 0.f;
}

// ---------------- e[b,t] = sum_h tanh(feat[b,t,h]+hp[b,h]) * w[h] -------------
__global__ void __launch_bounds__(128) e_kernel(
    const float* __restrict__ feat, const float* __restrict__ hp,
    const float* __restrict__ wsc, float* __restrict__ e)
{
    int t = blockIdx.x, b = blockIdx.y, tid = threadIdx.x;
    const float4* f4 = reinterpret_cast<const float4*>(feat + ((size_t)b * Tlen + t) * Hdim);
    const float4* h4 = reinterpret_cast<const float4*>(hp + (size_t)b * Hdim);
    const float4* w4 = reinterpret_cast<const float4*>(wsc);
    float4 f = f4[tid], h = h4[tid], w = w4[tid];   // 128 threads x 4 = 512 = H
    float s = tanhf(f.x + h.x) * w.x + tanhf(f.y + h.y) * w.y
            + tanhf(f.z + h.z) * w.z + tanhf(f.w + h.w) * w.w;
#pragma unroll
    for (int off = 16; off; off >>= 1) s += __shfl_down_sync(0xffffffffu, s, off);
    __shared__ float red[4];
    if ((tid & 31) == 0) red[tid >> 5] = s;
    __syncthreads();
    if (tid == 0) e[(size_t)b * Tlen + t] = red[0] + red[1] + red[2] + red[3];
}

// ---------------- softmax over T per batch row (in place) ----------------
__global__ void __launch_bounds__(128) softmax_kernel(float* __restrict__ e)
{
    int b = blockIdx.x, tid = threadIdx.x;
    float v = e[b * Tlen + tid];
    float m = v;
#pragma unroll
    for (int off = 16; off; off >>= 1) m = fmaxf(m, __shfl_xor_sync(0xffffffffu, m, off));
    __shared__ float red[4];
    if ((tid & 31) == 0) red[tid >> 5] = m;
    __syncthreads();
    m = fmaxf(fmaxf(red[0], red[1]), fmaxf(red[2], red[3]));
    float ex = __expf(v - m);
    float s = ex;
#pragma unroll
    for (int off = 16; off; off >>= 1) s += __shfl_xor_sync(0xffffffffu, s, off);
    __shared__ float red2[4];
    if ((tid & 31) == 0) red2[tid >> 5] = s;
    __syncthreads();
    s = red2[0] + red2[1] + red2[2] + red2[3];
    e[b * Tlen + tid] = ex / s;
}

// ---------------- ctx[b,i] = sum_t alpha[b,t]*batch_H[b,t,i] ----------------
__global__ void __launch_bounds__(128) ctx_kernel(
    const float* __restrict__ bh, const float* __restrict__ alpha,
    float* __restrict__ ctx)
{
    int b = blockIdx.x, tid = threadIdx.x;
    __shared__ float sal[Tlen];
    sal[tid] = alpha[b * Tlen + tid];
    __syncthreads();
    const float4* x4 = reinterpret_cast<const float4*>(bh + (size_t)b * Tlen * Idim);
    float4 acc = make_float4(0.f, 0.f, 0.f, 0.f);
#pragma unroll 4
    for (int t = 0; t < Tlen; t++) {
        float a = sal[t];
        float4 x = x4[(size_t)t * (Idim / 4) + tid];
        acc.x += a * x.x; acc.y += a * x.y; acc.z += a * x.z; acc.w += a * x.w;
    }
    reinterpret_cast<float4*>(ctx + (size_t)b * Idim)[tid] = acc;
}

// ---------------- gates init = b_ih + b_hh + W_ih[:, I + text[b,s]] -----------
__global__ void __launch_bounds__(256) initgates_kernel(
    const float* __restrict__ W_ih, const float* __restrict__ b_ih,
    const float* __restrict__ b_hh, const int* __restrict__ text,
    int s, float* __restrict__ gates)
{
    int b = blockIdx.y;
    int n = blockIdx.x * 256 + threadIdx.x;          // 8*256 = 2048 = 4H
    int ch = text[b * Snum + s];
    gates[(size_t)b * 4 * Hdim + n] =
        b_ih[n] + b_hh[n] + W_ih[(size_t)n * ICdim + Idim + ch];
}

// ---------------- LSTM cell elementwise + write out_h -------------------------
__global__ void __launch_bounds__(512) lstm_kernel(
    const float* __restrict__ gates, float* __restrict__ h,
    float* __restrict__ c, float* __restrict__ outh, int s)
{
    int b = blockIdx.x, j = threadIdx.x;
    const float* g = gates + (size_t)b * 4 * Hdim;
    float ig = g[j], fg = g[Hdim + j], gg = g[2 * Hdim + j], og = g[3 * Hdim + j];
    float si = 1.f / (1.f + __expf(-ig));
    float sf = 1.f / (1.f + __expf(-fg));
    float so = 1.f / (1.f + __expf(-og));
    float c2 = sf * c[b * Hdim + j] + si * tanhf(gg);
    float h2 = so * tanhf(c2);
    c[b * Hdim + j] = c2;
    h[b * Hdim + j] = h2;
    outh[((size_t)b * Snum + s) * Hdim + j] = h2;
}

// =============================================================================
extern "C" void kernel_launch(void* const* d_in, const int* in_sizes, int n_in,
                              void* d_out, int out_size)
{
    const float* batch_H = (const float*)d_in[0];
    const int*   text    = (const int*)  d_in[1];
    const float* W_feat  = (const float*)d_in[2];
    const float* W_hid   = (const float*)d_in[3];
    const float* b_hid   = (const float*)d_in[4];
    const float* w_score = (const float*)d_in[5];
    const float* W_ih    = (const float*)d_in[6];
    const float* W_hh    = (const float*)d_in[7];
    const float* b_ih    = (const float*)d_in[8];
    const float* b_hh    = (const float*)d_in[9];
    const float* W_gen   = (const float*)d_in[10];
    const float* b_gen   = (const float*)d_in[11];
    float* out = (float*)d_out;

    float *feat, *h, *c, *hp, *alpha, *ctx, *gates, *outh;
    cudaGetSymbolAddress((void**)&feat,  g_feat);
    cudaGetSymbolAddress((void**)&h,     g_h);
    cudaGetSymbolAddress((void**)&c,     g_c);
    cudaGetSymbolAddress((void**)&hp,    g_hp);
    cudaGetSymbolAddress((void**)&alpha, g_alpha);
    cudaGetSymbolAddress((void**)&ctx,   g_ctx);
    cudaGetSymbolAddress((void**)&gates, g_gates);
    cudaGetSymbolAddress((void**)&outh,  g_outh);

    // feat = batch_H @ W_feat^T  : M=B*T=65536, N=H=512, K=I=512
    sgemm_tn<0, 0><<<dim3(512 / 64, (Bsz * Tlen) / 128), 256>>>(
        batch_H, Idim, W_feat, Idim, feat, Hdim, nullptr,
        Bsz * Tlen, Hdim, Idim);

    zero_hc_kernel<<<(Bsz * Hdim) / 256, 256>>>();

    for (int s = 0; s < Snum; s++) {
        // hp = h @ W_hid^T + b_hid : 512x512x512
        sgemm_tn<0, 1><<<dim3(512 / 64, 512 / 128), 256>>>(
            h, Hdim, W_hid, Hdim, hp, Hdim, b_hid, Bsz, Hdim, Hdim);

        // scores
        e_kernel<<<dim3(Tlen, Bsz), 128>>>(feat, hp, w_score, alpha);
        softmax_kernel<<<Bsz, 128>>>(alpha);
        ctx_kernel<<<Bsz, 128>>>(batch_H, alpha, ctx);

        // gates = biases + onehot gather, then += ctx@W_ih[:, :I]^T, += h@W_hh^T
        initgates_kernel<<<dim3(2048 / 256, Bsz), 256>>>(W_ih, b_ih, b_hh, text, s, gates);
        sgemm_tn<1, 0><<<dim3(2048 / 64, 512 / 128), 256>>>(
            ctx, Idim, W_ih, ICdim, gates, 4 * Hdim, nullptr, Bsz, 4 * Hdim, Idim);
        sgemm_tn<1, 0><<<dim3(2048 / 64, 512 / 128), 256>>>(
            h, Hdim, W_hh, Hdim, gates, 4 * Hdim, nullptr, Bsz, 4 * Hdim, Hdim);

        lstm_kernel<<<Bsz, 512>>>(gates, h, c, outh, s);
    }

    // probs = out_h @ W_gen^T + b_gen : M=B*S=13312, N=97, K=512
    sgemm_tn<0, 1><<<dim3((Cnum + 63) / 64, (Bsz * Snum) / 128), 256>>>(
        outh, Hdim, W_gen, Hdim, out, Cnum, b_gen, Bsz * Snum, Cnum, Hdim);
}

// round 5
// speedup vs baseline: 1.2123x; 1.2123x over previous
#include <cuda_runtime.h>
#include <cuda_bf16.h>
#include <cstdint>

#define Bsz  512
#define Tlen 128
#define Idim 512
#define Hdim 512
#define Cnum 97
#define Snum 26
#define ICdim (Idim + Cnum)   // 609
#define RECN (Hdim + 4 * Hdim) // 2560: [hp | gates]

// ---------------- device scratch (allocation-free rule) ----------------
__device__ __align__(16) __nv_bfloat16 g_featb[(size_t)Bsz * Tlen * Hdim]; // 64 MiB
__device__ __align__(16) float g_h[Bsz * Hdim];
__device__ __align__(16) float g_c[Bsz * Hdim];
__device__ __align__(16) float g_rec[(size_t)Bsz * RECN];      // hp | gates
__device__ __align__(16) float g_ctx[Bsz * Idim];
__device__ __align__(16) float g_outh[(size_t)Bsz * Snum * Hdim];
__device__ __align__(16) float g_Wrec[(size_t)RECN * Hdim];    // [W_hid; W_hh]
__device__ __align__(16) float g_brec[RECN];                   // [b_hid | b_ih+b_hh]
__device__ __align__(16) float g_Wemb[(size_t)Cnum * 4 * Hdim];// transposed onehot cols

// ---------------- C store helpers ----------------
__device__ __forceinline__ void storeC(float* p, float v) { *p = v; }
__device__ __forceinline__ void storeC(__nv_bfloat16* p, float v) { *p = __float2bfloat16(v); }

// ---------------- generic fp32 GEMM: C[m,n] (+)= sum_k A[m,k]*B[n,k] (+bias[n]) --
// A:[M,K] row-major lda, B:[N,K] row-major ldb -> C = A*B^T. BM=128,BN=64,BK=16.
template<int ACC, int BIAS, int VECB, typename OutT>
__global__ void __launch_bounds__(256) sgemm_tn(
    const float* __restrict__ A, int lda,
    const float* __restrict__ Bm, int ldb,
    OutT* __restrict__ C, int ldc,
    const float* __restrict__ bias,
    int M, int N, int K)
{
    const int BM = 128, BN = 64, BK = 16;
    __shared__ float As[BK][BM];
    __shared__ float Bs[BK][BN];
    int tid = threadIdx.x;
    int tx = tid & 15;        // n direction
    int ty = tid >> 4;        // m direction
    int m0 = blockIdx.y * BM;
    int n0 = blockIdx.x * BN;

    float acc[8][4];
#pragma unroll
    for (int i = 0; i < 8; i++)
#pragma unroll
        for (int j = 0; j < 4; j++) acc[i][j] = 0.f;

    for (int k0 = 0; k0 < K; k0 += BK) {
        // A tile: 128x16 = 512 float4, 2 per thread
#pragma unroll
        for (int i = 0; i < 2; i++) {
            int lin = tid + i * 256;
            int row = lin >> 2;
            int kc  = (lin & 3) << 2;
            const float4 v = *reinterpret_cast<const float4*>(
                &A[(size_t)(m0 + row) * lda + k0 + kc]);
            As[kc + 0][row] = v.x; As[kc + 1][row] = v.y;
            As[kc + 2][row] = v.z; As[kc + 3][row] = v.w;
        }
        if (VECB) {
            // B tile: 64x16 = 256 float4, 1 per thread
            int row = tid >> 2;
            int kc  = (tid & 3) << 2;
            float4 v = make_float4(0.f, 0.f, 0.f, 0.f);
            if (n0 + row < N)
                v = *reinterpret_cast<const float4*>(
                    &Bm[(size_t)(n0 + row) * ldb + k0 + kc]);
            Bs[kc + 0][row] = v.x; Bs[kc + 1][row] = v.y;
            Bs[kc + 2][row] = v.z; Bs[kc + 3][row] = v.w;
        } else {
#pragma unroll
            for (int i = 0; i < 4; i++) {
                int lin = tid + i * 256;
                int kk = lin & 15;
                int nn = lin >> 4;
                float v = 0.f;
                if (n0 + nn < N) v = Bm[(size_t)(n0 + nn) * ldb + k0 + kk];
                Bs[kk][nn] = v;
            }
        }
        __syncthreads();
#pragma unroll
        for (int kk = 0; kk < BK; kk++) {
            float a[8], b[4];
#pragma unroll
            for (int i = 0; i < 8; i++) a[i] = As[kk][ty + i * 16];
#pragma unroll
            for (int j = 0; j < 4; j++) b[j] = Bs[kk][tx + j * 16];
#pragma unroll
            for (int i = 0; i < 8; i++)
#pragma unroll
                for (int j = 0; j < 4; j++)
                    acc[i][j] += a[i] * b[j];
        }
        __syncthreads();
    }
#pragma unroll
    for (int i = 0; i < 8; i++) {
        int m = m0 + ty + i * 16;
#pragma unroll
        for (int j = 0; j < 4; j++) {
            int n = n0 + tx + j * 16;
            if (n < N) {
                float v = acc[i][j];
                if (BIAS) v += bias[n];
                OutT* cp = &C[(size_t)m * ldc + n];
                if (ACC) v += *(const float*)cp;   // ACC only used with float OutT
                storeC(cp, v);
            }
        }
    }
}

// ---------------- packing (runs once per launch, ~trivial) ----------------
__global__ void __launch_bounds__(256) pack_rec_kernel(
    const float* __restrict__ W_hid, const float* __restrict__ W_hh,
    const float* __restrict__ b_hid, const float* __restrict__ b_ih,
    const float* __restrict__ b_hh)
{
    int i = blockIdx.x * 256 + threadIdx.x;   // grid covers RECN*Hdim = 1310720
    if (i < Hdim * Hdim) g_Wrec[i] = W_hid[i];
    else                 g_Wrec[i] = W_hh[i - Hdim * Hdim];
    if (i < RECN)
        g_brec[i] = (i < Hdim) ? b_hid[i] : (b_ih[i - Hdim] + b_hh[i - Hdim]);
}

__global__ void __launch_bounds__(256) pack_emb_kernel(const float* __restrict__ W_ih)
{
    int i = blockIdx.x * 256 + threadIdx.x;   // Cnum*4H = 198656
    if (i >= Cnum * 4 * Hdim) return;
    int c = i / (4 * Hdim);
    int n = i % (4 * Hdim);
    g_Wemb[i] = W_ih[(size_t)n * ICdim + Idim + c];
}

// ---------------- zero init of h,c ----------------
__global__ void zero_hc_kernel() {
    int i = blockIdx.x * 256 + threadIdx.x;
    g_h[i] = 0.f;
    g_c[i] = 0.f;
}

// ---------------- fused attention: e -> softmax -> ctx, one block per batch ---
__global__ void __launch_bounds__(256) attn_kernel(
    const __nv_bfloat16* __restrict__ feat,
    const float* __restrict__ bh,
    const float* __restrict__ grec,
    const float* __restrict__ wsc,
    float* __restrict__ ctx)
{
    int b = blockIdx.x, tid = threadIdx.x;
    int warp = tid >> 5, lane = tid & 31;
    __shared__ float2 s_hp[Hdim / 2];
    __shared__ float2 s_w[Hdim / 2];
    __shared__ float s_al[Tlen];
    __shared__ float s_red[8];

    s_hp[tid] = reinterpret_cast<const float2*>(grec + (size_t)b * RECN)[tid];
    s_w[tid]  = reinterpret_cast<const float2*>(wsc)[tid];
    __syncthreads();

    // scores: each of 8 warps handles 16 t values
    for (int t = warp; t < Tlen; t += 8) {
        const __nv_bfloat162* f2 = reinterpret_cast<const __nv_bfloat162*>(
            feat + ((size_t)b * Tlen + t) * Hdim);
        float s = 0.f;
#pragma unroll
        for (int j = 0; j < 8; j++) {
            int idx = lane + 32 * j;
            float2 vf = __bfloat1622float2(f2[idx]);
            float2 hp = s_hp[idx];
            float2 w  = s_w[idx];
            s += tanhf(vf.x + hp.x) * w.x + tanhf(vf.y + hp.y) * w.y;
        }
#pragma unroll
        for (int o = 16; o; o >>= 1) s += __shfl_down_sync(0xffffffffu, s, o);
        if (lane == 0) s_al[t] = s;
    }
    __syncthreads();

    // softmax over 128 (threads 0..127 = warps 0..3, fully active)
    if (tid < Tlen) {
        float v = s_al[tid];
        float m = v;
#pragma unroll
        for (int o = 16; o; o >>= 1) m = fmaxf(m, __shfl_xor_sync(0xffffffffu, m, o));
        if (lane == 0) s_red[warp] = m;
    }
    __syncthreads();
    if (tid < Tlen) {
        float m = fmaxf(fmaxf(s_red[0], s_red[1]), fmaxf(s_red[2], s_red[3]));
        float ex = __expf(s_al[tid] - m);
        float ss = ex;
#pragma unroll
        for (int o = 16; o; o >>= 1) ss += __shfl_xor_sync(0xffffffffu, ss, o);
        if (lane == 0) s_red[4 + warp] = ss;
        s_al[tid] = ex;
    }
    __syncthreads();
    float inv = 1.f / (s_red[4] + s_red[5] + s_red[6] + s_red[7]);

    // ctx: each thread owns 2 contiguous input cols
    float2 acc = make_float2(0.f, 0.f);
    const float2* x2 = reinterpret_cast<const float2*>(bh + (size_t)b * Tlen * Idim);
#pragma unroll 4
    for (int t = 0; t < Tlen; t++) {
        float a = s_al[t] * inv;
        float2 x = x2[(size_t)t * (Idim / 2) + tid];
        acc.x += a * x.x;
        acc.y += a * x.y;
    }
    reinterpret_cast<float2*>(ctx + (size_t)b * Idim)[tid] = acc;
}

// ---------------- LSTM cell elementwise (+ one-hot gather) -------------------
__global__ void __launch_bounds__(512) lstm_kernel(
    const float* __restrict__ grec, const float* __restrict__ Wemb,
    const int* __restrict__ text, int s,
    float* __restrict__ h, float* __restrict__ c, float* __restrict__ outh)
{
    int b = blockIdx.x, j = threadIdx.x;
    int ch = text[b * Snum + s];
    const float* g = grec + (size_t)b * RECN + Hdim;
    const float* e = Wemb + (size_t)ch * 4 * Hdim;
    float ig = g[j]            + e[j];
    float fg = g[Hdim + j]     + e[Hdim + j];
    float gg = g[2 * Hdim + j] + e[2 * Hdim + j];
    float og = g[3 * Hdim + j] + e[3 * Hdim + j];
    float si = 1.f / (1.f + __expf(-ig));
    float sf = 1.f / (1.f + __expf(-fg));
    float so = 1.f / (1.f + __expf(-og));
    float c2 = sf * c[b * Hdim + j] + si * tanhf(gg);
    float h2 = so * tanhf(c2);
    c[b * Hdim + j] = c2;
    h[b * Hdim + j] = h2;
    outh[((size_t)b * Snum + s) * Hdim + j] = h2;
}

// =============================================================================
extern "C" void kernel_launch(void* const* d_in, const int* in_sizes, int n_in,
                              void* d_out, int out_size)
{
    const float* batch_H = (const float*)d_in[0];
    const int*   text    = (const int*)  d_in[1];
    const float* W_feat  = (const float*)d_in[2];
    const float* W_hid   = (const float*)d_in[3];
    const float* b_hid   = (const float*)d_in[4];
    const float* w_score = (const float*)d_in[5];
    const float* W_ih    = (const float*)d_in[6];
    const float* W_hh    = (const float*)d_in[7];
    const float* b_ih    = (const float*)d_in[8];
    const float* b_hh    = (const float*)d_in[9];
    const float* W_gen   = (const float*)d_in[10];
    const float* b_gen   = (const float*)d_in[11];
    float* out = (float*)d_out;

    __nv_bfloat16* featb;
    float *h, *c, *rec, *ctx, *outh, *Wrec, *brec, *Wemb;
    cudaGetSymbolAddress((void**)&featb, g_featb);
    cudaGetSymbolAddress((void**)&h,     g_h);
    cudaGetSymbolAddress((void**)&c,     g_c);
    cudaGetSymbolAddress((void**)&rec,   g_rec);
    cudaGetSymbolAddress((void**)&ctx,   g_ctx);
    cudaGetSymbolAddress((void**)&outh,  g_outh);
    cudaGetSymbolAddress((void**)&Wrec,  g_Wrec);
    cudaGetSymbolAddress((void**)&brec,  g_brec);
    cudaGetSymbolAddress((void**)&Wemb,  g_Wemb);

    // one-time packs
    pack_rec_kernel<<<(RECN * Hdim) / 256, 256>>>(W_hid, W_hh, b_hid, b_ih, b_hh);
    pack_emb_kernel<<<(Cnum * 4 * Hdim + 255) / 256, 256>>>(W_ih);

    // feat = batch_H @ W_feat^T  (bf16 output): M=65536, N=512, K=512
    sgemm_tn<0, 0, 1, __nv_bfloat16><<<dim3(Hdim / 64, (Bsz * Tlen) / 128), 256>>>(
        batch_H, Idim, W_feat, Idim, featb, Hdim, nullptr,
        Bsz * Tlen, Hdim, Idim);

    zero_hc_kernel<<<(Bsz * Hdim) / 256, 256>>>();

    for (int s = 0; s < Snum; s++) {
        // rec = h @ [W_hid; W_hh]^T + [b_hid | b_ih+b_hh] : M=512, N=2560, K=512
        sgemm_tn<0, 1, 1, float><<<dim3(RECN / 64, Bsz / 128), 256>>>(
            h, Hdim, Wrec, Hdim, rec, RECN, brec, Bsz, RECN, Hdim);

        // fused attention -> ctx
        attn_kernel<<<Bsz, 256>>>(featb, batch_H, rec, w_score, ctx);

        // gates += ctx @ W_ih[:, :I]^T : M=512, N=2048, K=512 (ldb=609 -> scalar B)
        sgemm_tn<1, 0, 0, float><<<dim3((4 * Hdim) / 64, Bsz / 128), 256>>>(
            ctx, Idim, W_ih, ICdim, rec + Hdim, RECN, nullptr, Bsz, 4 * Hdim, Idim);

        lstm_kernel<<<Bsz, 512>>>(rec, Wemb, text, s, h, c, outh);
    }

    // probs = out_h @ W_gen^T + b_gen : M=13312, N=97, K=512
    sgemm_tn<0, 1, 1, float><<<dim3((Cnum + 63) / 64, (Bsz * Snum) / 128), 256>>>(
        outh, Hdim, W_gen, Hdim, out, Cnum, b_gen, Bsz * Snum, Cnum, Hdim);
}

// round 6
// speedup vs baseline: 2.0352x; 1.6787x over previous
#include <cuda_runtime.h>
#include <cuda_bf16.h>
#include <cuda_fp16.h>
#include <cstdint>

#define Bsz  512
#define Tlen 128
#define Idim 512
#define Hdim 512
#define Cnum 97
#define Snum 26
#define ICdim 609
#define KC  32          // fp32 K-chunk per stage
#define KCP 40          // padded bf16 row length (80 bytes) -> LDSM conflict-free

// ---------------- device scratch (allocation-free rule) ----------------
__device__ __align__(16) __half g_feat16[(size_t)Bsz * Tlen * Hdim];  // 64 MiB
__device__ __align__(16) __half g_bh16[(size_t)Bsz * Tlen * Idim];    // 64 MiB
__device__ __align__(16) float g_xh[Bsz * 1024];        // [ctx | h] per row
__device__ __align__(16) float g_hp[Bsz * Hdim];
__device__ __align__(16) float g_gates[Bsz * 2048];
__device__ __align__(16) float g_c[Bsz * Hdim];
__device__ __align__(16) float g_outh[(size_t)Bsz * Snum * Hdim];
__device__ __align__(16) float g_W2[2048 * 1024];       // [W_ih_x | W_hh]
__device__ __align__(16) float g_b2[2048];              // b_ih + b_hh
__device__ __align__(16) float g_Wemb[Cnum * 2048];     // transposed onehot cols

// ---------------- helpers ----------------
__device__ __forceinline__ void stC(float* p, float v)  { *p = v; }
__device__ __forceinline__ void stC(__half* p, float v) { *p = __float2half(v); }

__device__ __forceinline__ float tanh_fast(float x) {
    float y;
    asm("tanh.approx.f32 %0, %1;" : "=f"(y) : "f"(x));
    return y;
}

#define MMA_B16(d, a, b)                                                     \
    asm volatile(                                                            \
        "mma.sync.aligned.m16n8k16.row.col.f32.bf16.bf16.f32 "               \
        "{%0,%1,%2,%3},{%4,%5,%6,%7},{%8,%9},{%0,%1,%2,%3};"                 \
        : "+f"((d)[0]), "+f"((d)[1]), "+f"((d)[2]), "+f"((d)[3])             \
        : "r"((a)[0]), "r"((a)[1]), "r"((a)[2]), "r"((a)[3]),                \
          "r"((b)[0]), "r"((b)[1]))

#define LDSM_X4(r, addr)                                                     \
    asm volatile("ldmatrix.sync.aligned.m8n8.x4.shared.b16 {%0,%1,%2,%3},[%4];" \
        : "=r"((r)[0]), "=r"((r)[1]), "=r"((r)[2]), "=r"((r)[3]) : "r"(addr))

// ============ split-bf16 tensor-core GEMM: C = A*B^T (+bias) =================
// A:[M,K] fp32 row-major lda, B:[N,K] fp32 row-major ldb.
// BM=128, BN=128, KC=32, 256 threads, warp grid 2(m)x4(n), warp tile 64x32.
// fp32 split on the fly into hi/lo bf16; 3 MMAs recover ~fp32 precision.
template<int BIAS, typename OutT>
__global__ void __launch_bounds__(256, 2) bgemm(
    const float* __restrict__ A, int lda,
    const float* __restrict__ Bm, int ldb,
    OutT* __restrict__ C, int ldc,
    const float* __restrict__ bias,
    int N, int K)
{
    __shared__ __align__(16) __nv_bfloat16 sA[2][128 * KCP];  // [hi, lo]
    __shared__ __align__(16) __nv_bfloat16 sB[2][128 * KCP];

    const int tid = threadIdx.x, lane = tid & 31, warp = tid >> 5;
    const int wm = (warp >> 2) * 64, wn = (warp & 3) * 32;
    const int m0 = blockIdx.y * 128, n0 = blockIdx.x * 128;

    float acc[4][4][4];
#pragma unroll
    for (int i = 0; i < 4; i++)
#pragma unroll
        for (int j = 0; j < 4; j++)
#pragma unroll
            for (int r = 0; r < 4; r++) acc[i][j][r] = 0.f;

    uint32_t saB[2] = { (uint32_t)__cvta_generic_to_shared(&sA[0][0]),
                        (uint32_t)__cvta_generic_to_shared(&sA[1][0]) };
    uint32_t sbB[2] = { (uint32_t)__cvta_generic_to_shared(&sB[0][0]),
                        (uint32_t)__cvta_generic_to_shared(&sB[1][0]) };

    // LDSM lane-address components (byte offsets; row stride = KCP*2 = 80 B)
    const uint32_t aOff = (uint32_t)((wm + (lane & 15)) * (KCP * 2) + (lane >> 4) * 16);
    const uint32_t bOff = (uint32_t)((wn + ((lane >> 4) << 3) + (lane & 7)) * (KCP * 2)
                                     + ((lane >> 3) & 1) * 16);

    for (int k0 = 0; k0 < K; k0 += KC) {
        // ---- load + split A tile (128 x 32 fp32) ----
#pragma unroll
        for (int i = 0; i < 4; i++) {
            int idx = tid + i * 256;
            int r = idx >> 3, c = (idx & 7) << 2;
            float4 v = *reinterpret_cast<const float4*>(
                &A[(size_t)(m0 + r) * lda + k0 + c]);
            __nv_bfloat162 h0 = __floats2bfloat162_rn(v.x, v.y);
            __nv_bfloat162 h1 = __floats2bfloat162_rn(v.z, v.w);
            float2 f0 = __bfloat1622float2(h0), f1 = __bfloat1622float2(h1);
            __nv_bfloat162 l0 = __floats2bfloat162_rn(v.x - f0.x, v.y - f0.y);
            __nv_bfloat162 l1 = __floats2bfloat162_rn(v.z - f1.x, v.w - f1.y);
            *reinterpret_cast<__nv_bfloat162*>(&sA[0][r * KCP + c])     = h0;
            *reinterpret_cast<__nv_bfloat162*>(&sA[0][r * KCP + c + 2]) = h1;
            *reinterpret_cast<__nv_bfloat162*>(&sA[1][r * KCP + c])     = l0;
            *reinterpret_cast<__nv_bfloat162*>(&sA[1][r * KCP + c + 2]) = l1;
        }
        // ---- load + split B tile (128 x 32 fp32, N-guarded) ----
#pragma unroll
        for (int i = 0; i < 4; i++) {
            int idx = tid + i * 256;
            int r = idx >> 3, c = (idx & 7) << 2;
            float4 v = make_float4(0.f, 0.f, 0.f, 0.f);
            if (n0 + r < N)
                v = *reinterpret_cast<const float4*>(
                    &Bm[(size_t)(n0 + r) * ldb + k0 + c]);
            __nv_bfloat162 h0 = __floats2bfloat162_rn(v.x, v.y);
            __nv_bfloat162 h1 = __floats2bfloat162_rn(v.z, v.w);
            float2 f0 = __bfloat1622float2(h0), f1 = __bfloat1622float2(h1);
            __nv_bfloat162 l0 = __floats2bfloat162_rn(v.x - f0.x, v.y - f0.y);
            __nv_bfloat162 l1 = __floats2bfloat162_rn(v.z - f1.x, v.w - f1.y);
            *reinterpret_cast<__nv_bfloat162*>(&sB[0][r * KCP + c])     = h0;
            *reinterpret_cast<__nv_bfloat162*>(&sB[0][r * KCP + c + 2]) = h1;
            *reinterpret_cast<__nv_bfloat162*>(&sB[1][r * KCP + c])     = l0;
            *reinterpret_cast<__nv_bfloat162*>(&sB[1][r * KCP + c + 2]) = l1;
        }
        __syncthreads();

#pragma unroll
        for (int k16 = 0; k16 < 2; k16++) {
            uint32_t af[2][4][4];
#pragma unroll
            for (int t = 0; t < 2; t++)
#pragma unroll
                for (int mt = 0; mt < 4; mt++) {
                    uint32_t ad = saB[t] + aOff + (uint32_t)(mt * 16 * KCP * 2 + k16 * 32);
                    LDSM_X4(af[t][mt], ad);
                }
#pragma unroll
            for (int p = 0; p < 2; p++) {
                uint32_t bf[2][2][2];   // [term][ntile-in-pair][2 regs]
#pragma unroll
                for (int t = 0; t < 2; t++) {
                    uint32_t bd = sbB[t] + bOff + (uint32_t)(p * 16 * KCP * 2 + k16 * 32);
                    uint32_t r4[4];
                    LDSM_X4(r4, bd);
                    bf[t][0][0] = r4[0]; bf[t][0][1] = r4[1];
                    bf[t][1][0] = r4[2]; bf[t][1][1] = r4[3];
                }
#pragma unroll
                for (int mt = 0; mt < 4; mt++)
#pragma unroll
                    for (int q = 0; q < 2; q++) {
                        int nt = 2 * p + q;
                        MMA_B16(acc[mt][nt], af[0][mt], bf[0][q]);  // hi*hi
                        MMA_B16(acc[mt][nt], af[0][mt], bf[1][q]);  // hi*lo
                        MMA_B16(acc[mt][nt], af[1][mt], bf[0][q]);  // lo*hi
                    }
            }
        }
        __syncthreads();
    }

    // ---- epilogue ----
    const int gid = lane >> 2, tig = lane & 3;
#pragma unroll
    for (int mt = 0; mt < 4; mt++) {
        int r0 = m0 + wm + mt * 16 + gid;
#pragma unroll
        for (int nt = 0; nt < 4; nt++) {
            int col = n0 + wn + nt * 8 + 2 * tig;
            float b0 = 0.f, b1 = 0.f;
            if (BIAS) {
                if (col < N)     b0 = bias[col];
                if (col + 1 < N) b1 = bias[col + 1];
            }
            if (col < N) {
                stC(&C[(size_t)r0 * ldc + col],       acc[mt][nt][0] + b0);
                stC(&C[(size_t)(r0 + 8) * ldc + col], acc[mt][nt][2] + b0);
            }
            if (col + 1 < N) {
                stC(&C[(size_t)r0 * ldc + col + 1],       acc[mt][nt][1] + b1);
                stC(&C[(size_t)(r0 + 8) * ldc + col + 1], acc[mt][nt][3] + b1);
            }
        }
    }
}

// ---------------- packing / init (once per launch) ----------------
__global__ void __launch_bounds__(256) pack_W2_kernel(
    const float* __restrict__ W_ih, const float* __restrict__ W_hh,
    const float* __restrict__ b_ih, const float* __restrict__ b_hh)
{
    int i = blockIdx.x * 256 + threadIdx.x;   // 2048*1024
    int n = i >> 10, k = i & 1023;
    g_W2[i] = (k < 512) ? W_ih[(size_t)n * ICdim + k]
                        : W_hh[(size_t)n * 512 + (k - 512)];
    if (i < 2048) g_b2[i] = b_ih[i] + b_hh[i];
}

__global__ void __launch_bounds__(256) pack_emb_kernel(const float* __restrict__ W_ih)
{
    int i = blockIdx.x * 256 + threadIdx.x;   // Cnum*2048
    if (i >= Cnum * 2048) return;
    int c = i >> 11, n = i & 2047;
    g_Wemb[i] = W_ih[(size_t)n * ICdim + 512 + c];
}

__global__ void __launch_bounds__(256) pack_bh16_kernel(const float* __restrict__ bh)
{
    int i = blockIdx.x * 256 + threadIdx.x;
    float4 v = reinterpret_cast<const float4*>(bh)[i];
    reinterpret_cast<__half2*>(g_bh16)[2 * i]     = __floats2half2_rn(v.x, v.y);
    reinterpret_cast<__half2*>(g_bh16)[2 * i + 1] = __floats2half2_rn(v.z, v.w);
}

__global__ void __launch_bounds__(256) zero_init_kernel()
{
    int i = blockIdx.x * 256 + threadIdx.x;   // covers Bsz*1024
    g_xh[i] = 0.f;
    if (i < Bsz * Hdim) g_c[i] = 0.f;
}

// ---------------- fused attention: e -> softmax -> ctx ----------------------
__global__ void __launch_bounds__(256) attn_kernel(
    const __half* __restrict__ feat,
    const __half* __restrict__ bh,
    const float* __restrict__ hp,
    const float* __restrict__ wsc,
    float* __restrict__ xh)
{
    int b = blockIdx.x, tid = threadIdx.x;
    int warp = tid >> 5, lane = tid & 31;
    __shared__ float2 s_hp[Hdim / 2];
    __shared__ float2 s_w[Hdim / 2];
    __shared__ float s_al[Tlen];
    __shared__ float s_red[8];

    s_hp[tid] = reinterpret_cast<const float2*>(hp + (size_t)b * Hdim)[tid];
    s_w[tid]  = reinterpret_cast<const float2*>(wsc)[tid];
    __syncthreads();

    for (int t = warp; t < Tlen; t += 8) {
        const __half2* f2 = reinterpret_cast<const __half2*>(
            feat + ((size_t)b * Tlen + t) * Hdim);
        float s = 0.f;
#pragma unroll
        for (int j = 0; j < 8; j++) {
            int idx = lane + 32 * j;
            float2 vf = __half22float2(f2[idx]);
            float2 hpv = s_hp[idx];
            float2 w   = s_w[idx];
            s += tanh_fast(vf.x + hpv.x) * w.x + tanh_fast(vf.y + hpv.y) * w.y;
        }
#pragma unroll
        for (int o = 16; o; o >>= 1) s += __shfl_down_sync(0xffffffffu, s, o);
        if (lane == 0) s_al[t] = s;
    }
    __syncthreads();

    if (tid < Tlen) {
        float v = s_al[tid];
        float m = v;
#pragma unroll
        for (int o = 16; o; o >>= 1) m = fmaxf(m, __shfl_xor_sync(0xffffffffu, m, o));
        if (lane == 0) s_red[warp] = m;
    }
    __syncthreads();
    if (tid < Tlen) {
        float m = fmaxf(fmaxf(s_red[0], s_red[1]), fmaxf(s_red[2], s_red[3]));
        float ex = __expf(s_al[tid] - m);
        float ss = ex;
#pragma unroll
        for (int o = 16; o; o >>= 1) ss += __shfl_xor_sync(0xffffffffu, ss, o);
        if (lane == 0) s_red[4 + warp] = ss;
        s_al[tid] = ex;
    }
    __syncthreads();
    float inv = 1.f / (s_red[4] + s_red[5] + s_red[6] + s_red[7]);

    float2 acc = make_float2(0.f, 0.f);
    const __half2* x2 = reinterpret_cast<const __half2*>(bh + (size_t)b * Tlen * Idim);
#pragma unroll 4
    for (int t = 0; t < Tlen; t++) {
        float a = s_al[t] * inv;
        float2 x = __half22float2(x2[(size_t)t * (Idim / 2) + tid]);
        acc.x += a * x.x;
        acc.y += a * x.y;
    }
    reinterpret_cast<float2*>(xh + (size_t)b * 1024)[tid] = acc;
}

// ---------------- LSTM cell elementwise (+ one-hot gather) -------------------
__global__ void __launch_bounds__(512) lstm_kernel(
    const float* __restrict__ gates, const float* __restrict__ Wemb,
    const int* __restrict__ text, int s,
    float* __restrict__ xh, float* __restrict__ c, float* __restrict__ outh)
{
    int b = blockIdx.x, j = threadIdx.x;
    int ch = text[b * Snum + s];
    const float* g = gates + (size_t)b * 2048;
    const float* e = Wemb + (size_t)ch * 2048;
    float ig = g[j]            + e[j];
    float fg = g[Hdim + j]     + e[Hdim + j];
    float gg = g[2 * Hdim + j] + e[2 * Hdim + j];
    float og = g[3 * Hdim + j] + e[3 * Hdim + j];
    float si = 1.f / (1.f + __expf(-ig));
    float sf = 1.f / (1.f + __expf(-fg));
    float so = 1.f / (1.f + __expf(-og));
    float c2 = sf * c[b * Hdim + j] + si * tanhf(gg);
    float h2 = so * tanhf(c2);
    c[b * Hdim + j] = c2;
    xh[(size_t)b * 1024 + 512 + j] = h2;
    outh[((size_t)b * Snum + s) * Hdim + j] = h2;
}

// =============================================================================
extern "C" void kernel_launch(void* const* d_in, const int* in_sizes, int n_in,
                              void* d_out, int out_size)
{
    const float* batch_H = (const float*)d_in[0];
    const int*   text    = (const int*)  d_in[1];
    const float* W_feat  = (const float*)d_in[2];
    const float* W_hid   = (const float*)d_in[3];
    const float* b_hid   = (const float*)d_in[4];
    const float* w_score = (const float*)d_in[5];
    const float* W_ih    = (const float*)d_in[6];
    const float* W_hh    = (const float*)d_in[7];
    const float* b_ih    = (const float*)d_in[8];
    const float* b_hh    = (const float*)d_in[9];
    const float* W_gen   = (const float*)d_in[10];
    const float* b_gen   = (const float*)d_in[11];
    float* out = (float*)d_out;

    __half *feat16, *bh16;
    float *xh, *hp, *gates, *cc, *outh, *W2, *b2, *Wemb;
    cudaGetSymbolAddress((void**)&feat16, g_feat16);
    cudaGetSymbolAddress((void**)&bh16,   g_bh16);
    cudaGetSymbolAddress((void**)&xh,     g_xh);
    cudaGetSymbolAddress((void**)&hp,     g_hp);
    cudaGetSymbolAddress((void**)&gates,  g_gates);
    cudaGetSymbolAddress((void**)&cc,     g_c);
    cudaGetSymbolAddress((void**)&outh,   g_outh);
    cudaGetSymbolAddress((void**)&W2,     g_W2);
    cudaGetSymbolAddress((void**)&b2,     g_b2);
    cudaGetSymbolAddress((void**)&Wemb,   g_Wemb);

    // one-time packs + init
    pack_W2_kernel<<<(2048 * 1024) / 256, 256>>>(W_ih, W_hh, b_ih, b_hh);
    pack_emb_kernel<<<(Cnum * 2048 + 255) / 256, 256>>>(W_ih);
    pack_bh16_kernel<<<(Bsz * Tlen * Idim / 4) / 256, 256>>>(batch_H);
    zero_init_kernel<<<(Bsz * 1024) / 256, 256>>>();

    // feat16 = batch_H @ W_feat^T : M=65536, N=512, K=512 (half out)
    bgemm<0, __half><<<dim3(4, (Bsz * Tlen) / 128), 256>>>(
        batch_H, Idim, W_feat, Idim, feat16, Hdim, nullptr, Hdim, Idim);

    for (int s = 0; s < Snum; s++) {
        // hp = h @ W_hid^T + b_hid : M=512, N=512, K=512  (h = xh[:,512:])
        bgemm<1, float><<<dim3(4, 4), 256>>>(
            xh + 512, 1024, W_hid, Hdim, hp, Hdim, b_hid, Hdim, Hdim);

        attn_kernel<<<Bsz, 256>>>(feat16, bh16, hp, w_score, xh);

        // gates = [ctx|h] @ [W_ih_x|W_hh]^T + (b_ih+b_hh) : M=512,N=2048,K=1024
        bgemm<1, float><<<dim3(16, 4), 256>>>(
            xh, 1024, W2, 1024, gates, 2048, b2, 2048, 1024);

        lstm_kernel<<<Bsz, 512>>>(gates, Wemb, text, s, xh, cc, outh);
    }

    // probs = out_h @ W_gen^T + b_gen : M=13312, N=97, K=512
    bgemm<1, float><<<dim3(1, (Bsz * Snum) / 128), 256>>>(
        outh, Hdim, W_gen, Hdim, out, Cnum, b_gen, Cnum, Hdim);
}